// round 10
// baseline (speedup 1.0000x reference)
#include <cuda_runtime.h>
#include <cuda_fp16.h>
#include <math.h>
#include <stdint.h>

#define BB 512
#define TT 128
#define FF 1024
#define HH 1024
#define NOUT 256
#define FOURH 4096
#define BT 65536
#define NCTA_COL 32
#define NCTA_ROW 8

typedef __half h16;

// ---------------------------------------------------------------------------
// Device-global scratch (sorted-batch order unless noted)
// ---------------------------------------------------------------------------
__device__ float g_xw[(size_t)BT * FOURH];     // X @ Wx + b, gate-interleaved cols
__device__ float g_c[BB * HH];
__device__ float g_h[BB * HH];
__device__ float g_bias[FOURH];                // permuted bias
__device__ h16   g_x16[(size_t)BT * FF];       // X as fp16 (ORIGINAL batch order)
__device__ h16   g_f16[(size_t)BT * HH];       // masked h outputs (zero-init!)
__device__ h16   g_h16[2][BB * HH];            // double-buffered h state, fp16
__device__ h16   g_wx_hi[(size_t)FOURH * FF];  // Wx^T [4H,F] K-major, interleaved rows
__device__ h16   g_wh_hi[(size_t)FOURH * HH];
__device__ h16   g_wh_lo[(size_t)FOURH * HH];
__device__ h16   g_wo_hi[NOUT * HH];
__device__ int   g_perm[BB];                   // sorted idx -> original idx
__device__ int   g_seqp[BB];                   // seq_len in sorted order (descending)
__device__ int   g_nact[TT];                   // #batches with seq_len > t
__device__ unsigned g_bar_cnt[TT];             // per-step barrier counters (reset each replay)
__device__ unsigned g_bar_rel[TT];             // per-step release flags

// ---------------------------------------------------------------------------
// Baseline-PTX helpers (legal on plain sm_103 target)
// ---------------------------------------------------------------------------
__device__ __forceinline__ uint32_t smem_u32(const void* p) {
    uint32_t a;
    asm("{ .reg .u64 t; cvta.to.shared.u64 t, %1; cvt.u32.u64 %0, t; }"
        : "=r"(a) : "l"(p));
    return a;
}
__device__ __forceinline__ void cp16(uint32_t dst, const void* src) {
    asm volatile("cp.async.cg.shared.global [%0], [%1], 16;"
                 :: "r"(dst), "l"(src) : "memory");
}
__device__ __forceinline__ void ldsm4(uint32_t* r, uint32_t addr) {
    asm volatile("ldmatrix.sync.aligned.m8n8.x4.shared.b16 {%0,%1,%2,%3}, [%4];"
                 : "=r"(r[0]), "=r"(r[1]), "=r"(r[2]), "=r"(r[3]) : "r"(addr));
}
__device__ __forceinline__ void mma16816(float* d, const uint32_t* a, const uint32_t* b) {
    asm volatile(
        "mma.sync.aligned.m16n8k16.row.col.f32.f16.f16.f32 "
        "{%0,%1,%2,%3}, {%4,%5,%6,%7}, {%8,%9}, {%0,%1,%2,%3};"
        : "+f"(d[0]), "+f"(d[1]), "+f"(d[2]), "+f"(d[3])
        : "r"(a[0]), "r"(a[1]), "r"(a[2]), "r"(a[3]), "r"(b[0]), "r"(b[1]));
}

// ---------------------------------------------------------------------------
// GEMM tile machinery. BN=128, BK=32, 256 threads (8 warps 2x4).
// BM = MT*32. NB = B terms. NST = stages. A pointer pre-offset (row 0 = tile top).
// ---------------------------------------------------------------------------
#define ROWB 80
#define OP_BYTES (128 * ROWB)              // 10240

template <int MT, int NB>
__device__ __forceinline__ void load_stage(
    uint32_t stg, const h16* __restrict__ A,
    const h16* __restrict__ Bh, const h16* __restrict__ Bl,
    int n0, int k0, int K, int tid)
{
    constexpr int BM = MT * 32;
    constexpr uint32_t OFFB = (uint32_t)BM * ROWB;
#pragma unroll
    for (int i = 0; i < BM * 4 / 256; i++) {
        const int c = tid + i * 256;
        const int row = c >> 2;
        const int seg = c & 3;
        cp16(stg + (uint32_t)(row * ROWB + seg * 16),
             A + (size_t)row * K + k0 + seg * 8);
    }
#pragma unroll
    for (int i = 0; i < 2; i++) {
        const int c = tid + i * 256;
        const int row = c >> 2;
        const int seg = c & 3;
        const uint32_t soff = (uint32_t)(row * ROWB + seg * 16);
        const size_t gb = (size_t)(n0 + row) * K + k0 + seg * 8;
        cp16(stg + OFFB + soff, Bh + gb);
        if (NB == 2) cp16(stg + OFFB + OP_BYTES + soff, Bl + gb);
    }
}

template <int MT, int NB, int NST>
__device__ __forceinline__ void gemm_mainloop(
    uint32_t SM, const h16* __restrict__ A,
    const h16* __restrict__ Bh, const h16* __restrict__ Bl,
    int n0, int K, int tid, float acc[MT][4][4])
{
    constexpr uint32_t OFFB = (uint32_t)(MT * 32) * ROWB;
    constexpr uint32_t STG_B = OFFB + NB * OP_BYTES;
    const int lane = tid & 31;
    const int wid  = tid >> 5;
    const int wm   = wid & 1;
    const int wn   = wid >> 1;
    const int NC = K >> 5;

#pragma unroll
    for (int s = 0; s < NST - 1; s++) {
        load_stage<MT, NB>(SM + s * STG_B, A, Bh, Bl, n0, s * 32, K, tid);
        asm volatile("cp.async.commit_group;" ::: "memory");
    }

    const int arow = wm * (MT * 16) + (lane & 15);
    const uint32_t akoff = (uint32_t)((lane >> 4) * 16);
    const int bsel = lane >> 3;
    const int bn = wn * 32 + ((bsel >> 1) << 3) + (lane & 7);
    const uint32_t bkoff = (uint32_t)((bsel & 1) * 16);

    for (int it = 0; it < NC; it++) {
        asm volatile("cp.async.wait_group %0;" :: "n"(NST - 2) : "memory");
        __syncthreads();

        const int nx = it + NST - 1;
        if (nx < NC)
            load_stage<MT, NB>(SM + (uint32_t)(nx % NST) * STG_B,
                               A, Bh, Bl, n0, nx * 32, K, tid);
        asm volatile("cp.async.commit_group;" ::: "memory");

        const uint32_t stg = SM + (uint32_t)(it % NST) * STG_B;
#pragma unroll
        for (int ks = 0; ks < 2; ks++) {
            uint32_t ah[MT][4], bh[4][2], bl[4][2];
            const uint32_t ak = (uint32_t)(ks * 32) + akoff;
#pragma unroll
            for (int mt = 0; mt < MT; mt++)
                ldsm4(ah[mt], stg + (uint32_t)((arow + mt * 16) * ROWB) + ak);
            const uint32_t bk = (uint32_t)(ks * 32) + bkoff;
#pragma unroll
            for (int np = 0; np < 2; np++) {
                const uint32_t bd = stg + OFFB + (uint32_t)((bn + np * 16) * ROWB) + bk;
                uint32_t tr[4];
                ldsm4(tr, bd);
                bh[2 * np][0] = tr[0]; bh[2 * np][1] = tr[1];
                bh[2 * np + 1][0] = tr[2]; bh[2 * np + 1][1] = tr[3];
                if (NB == 2) {
                    ldsm4(tr, bd + OP_BYTES);
                    bl[2 * np][0] = tr[0]; bl[2 * np][1] = tr[1];
                    bl[2 * np + 1][0] = tr[2]; bl[2 * np + 1][1] = tr[3];
                }
            }
#pragma unroll
            for (int mt = 0; mt < MT; mt++)
#pragma unroll
                for (int nt = 0; nt < 4; nt++) {
                    mma16816(acc[mt][nt], ah[mt], bh[nt]);
                    if (NB == 2) mma16816(acc[mt][nt], ah[mt], bl[nt]);
                }
        }
    }
}

// Common epilogue: acc -> C (row-stride N) with optional bias indexed by n0+col.
template <int MT>
__device__ __forceinline__ void store_acc(
    float acc[MT][4][4], float* __restrict__ C, const float* __restrict__ bias,
    int N, int n0, int tid)
{
    const int lane = tid & 31;
    const int wid  = tid >> 5;
    const int wm   = wid & 1;
    const int wn   = wid >> 1;
    const int colq = (lane & 3) * 2;
    const int rowq = lane >> 2;
#pragma unroll
    for (int nt = 0; nt < 4; nt++) {
        const int col = wn * 32 + nt * 8 + colq;
        float bx = 0.f, by = 0.f;
        if (bias) { float2 bv = *(const float2*)(bias + n0 + col); bx = bv.x; by = bv.y; }
#pragma unroll
        for (int mt = 0; mt < MT; mt++) {
            const int r0 = wm * (MT * 16) + mt * 16 + rowq;
            *(float2*)(C + (size_t)r0 * N + n0 + col) =
                make_float2(acc[mt][nt][0] + bx, acc[mt][nt][1] + by);
            *(float2*)(C + (size_t)(r0 + 8) * N + n0 + col) =
                make_float2(acc[mt][nt][2] + bx, acc[mt][nt][3] + by);
        }
    }
}

// ---------------------------------------------------------------------------
// XW GEMM: BM=64 tiles over (batch, 64-step t-range); skip if t0 >= seq.
// ---------------------------------------------------------------------------
#define SMEM_X (4 * (64 * ROWB + OP_BYTES))     // 61440
__global__ __launch_bounds__(256, 2)
void gemm_xw()
{
    extern __shared__ char smem_raw[];
    const uint32_t SM = smem_u32(smem_raw);
    const int tid = threadIdx.x;
    const int my = blockIdx.y;
    const int bp = my >> 1;
    const int t0 = (my & 1) * 64;
    if (t0 >= g_seqp[bp]) return;
    const int n0 = blockIdx.x * 128;

    const h16* A = g_x16 + ((size_t)g_perm[bp] * TT + t0) * FF;
    float* C = g_xw + ((size_t)bp * TT + t0) * FOURH;

    float acc[2][4][4];
#pragma unroll
    for (int a = 0; a < 2; a++)
#pragma unroll
        for (int b = 0; b < 4; b++)
#pragma unroll
            for (int cc = 0; cc < 4; cc++) acc[a][b][cc] = 0.0f;

    gemm_mainloop<2, 1, 4>(SM, A, g_wx_hi, nullptr, n0, FF, tid, acc);
    store_acc<2>(acc, C, g_bias, FOURH, n0, tid);
}

// ---------------------------------------------------------------------------
// Head GEMM: BM=64 tiles; skipped tiles emit bias rows. Output in ORIGINAL order.
// ---------------------------------------------------------------------------
__global__ __launch_bounds__(256, 2)
void gemm_head(const float* __restrict__ bout, float* __restrict__ out)
{
    extern __shared__ char smem_raw[];
    const uint32_t SM = smem_u32(smem_raw);
    const int tid = threadIdx.x;
    const int my = blockIdx.y;
    const int bp = my >> 1;
    const int t0 = (my & 1) * 64;
    const int n0 = blockIdx.x * 128;
    float* C = out + ((size_t)g_perm[bp] * TT + t0) * NOUT;

    if (t0 >= g_seqp[bp]) {
#pragma unroll
        for (int i = 0; i < 8; i++) {
            const int idx = i * 256 + tid;
            const int r = idx >> 5;
            const int c = (idx & 31) * 4;
            *(float4*)(C + (size_t)r * NOUT + n0 + c) = *(const float4*)(bout + n0 + c);
        }
        return;
    }

    const h16* A = g_f16 + ((size_t)bp * TT + t0) * HH;
    float acc[2][4][4];
#pragma unroll
    for (int a = 0; a < 2; a++)
#pragma unroll
        for (int b = 0; b < 4; b++)
#pragma unroll
            for (int cc = 0; cc < 4; cc++) acc[a][b][cc] = 0.0f;

    gemm_mainloop<2, 1, 4>(SM, A, g_wo_hi, nullptr, n0, HH, tid, acc);
    store_acc<2>(acc, C, bout, NOUT, n0, tid);
}

// ---------------------------------------------------------------------------
// PERSISTENT fused recurrence: one launch, 256 co-resident CTAs, per-step
// device barrier. Monotone early-exit for inactive row tiles.
// ---------------------------------------------------------------------------
#define SMEM_REC (3 * (64 * ROWB + 2 * OP_BYTES))   // 76800
__device__ __forceinline__ float sigf(float x) { return 1.0f / (1.0f + expf(-x)); }
__device__ __forceinline__ void splitw(float v, h16& hi, h16& lo) {
    hi = __float2half(v);
    lo = __float2half(v - __half2float(hi));
}

#define ZPITCH 132

__global__ __launch_bounds__(256, 2)
void lstm_persistent()
{
    extern __shared__ char smem_raw[];
    const uint32_t SM = smem_u32(smem_raw);
    float* zs = (float*)smem_raw;
    const int tid  = threadIdx.x;
    const int lane = tid & 31;
    const int wid  = tid >> 5;
    const int wm   = wid & 1;
    const int wn   = wid >> 1;
    const int n0 = blockIdx.x * 128;
    const int m0 = blockIdx.y * 64;
    const int colq = (lane & 3) * 2;
    const int rowq = lane >> 2;

    for (int t = 0; t < TT; t++) {
        const int nact = g_nact[t];
        if (m0 >= nact) return;             // nact is non-increasing -> done forever

        const h16* __restrict__ h_rd = g_h16[t & 1] + (size_t)m0 * HH;
        h16* __restrict__ h_wr = g_h16[(t + 1) & 1];

        float acc[2][4][4];
#pragma unroll
        for (int a = 0; a < 2; a++)
#pragma unroll
            for (int b = 0; b < 4; b++)
#pragma unroll
                for (int cc = 0; cc < 4; cc++) acc[a][b][cc] = 0.0f;

        gemm_mainloop<2, 2, 3>(SM, h_rd, g_wh_hi, g_wh_lo, n0, HH, tid, acc);

        __syncthreads();

#pragma unroll
        for (int nt = 0; nt < 4; nt++) {
            const int col = wn * 32 + nt * 8 + colq;
#pragma unroll
            for (int mt = 0; mt < 2; mt++) {
                const int r0 = wm * 32 + mt * 16 + rowq;
                *(float2*)&zs[r0 * ZPITCH + col] = make_float2(acc[mt][nt][0], acc[mt][nt][1]);
                *(float2*)&zs[(r0 + 8) * ZPITCH + col] = make_float2(acc[mt][nt][2], acc[mt][nt][3]);
            }
        }
        __syncthreads();

#pragma unroll
        for (int i = 0; i < 8; i++) {
            const int idx = i * 256 + tid;
            const int r = idx >> 5;
            const int u = idx & 31;
            const int b = m0 + r;
            const int hx = (n0 >> 2) + u;

            float4 z4 = *(float4*)&zs[r * ZPITCH + 4 * u];
            float4 x4 = *(const float4*)(g_xw + ((size_t)b * TT + t) * FOURH + n0 + 4 * u);

            const float zi = z4.x + x4.x;
            const float zj = z4.y + x4.y;
            const float zf = z4.z + x4.z;
            const float zo = z4.w + x4.w;

            const size_t si = (size_t)b * HH + hx;
            const float c = g_c[si];
            const float hprev = g_h[si];
            const bool m = t < g_seqp[b];

            const float nc = c * sigf(zf + 1.0f) + sigf(zi) * tanhf(zj);
            const float nh = tanhf(nc) * sigf(zo);

            const float co = m ? nc : c;
            const float ho = m ? nh : hprev;
            const float fe = m ? nh : 0.0f;

            g_c[si] = co;
            g_h[si] = ho;
            h_wr[si] = __float2half(ho);
            g_f16[((size_t)b * TT + t) * HH + hx] = __float2half(fe);
        }

        // grid barrier between steps (participants = CTAs active at step t)
        if (t < TT - 1) {
            const unsigned expected = (unsigned)(NCTA_COL * ((nact + 63) >> 6));
            __syncthreads();
            if (tid == 0) {
                __threadfence();
                unsigned tk = atomicAdd(&g_bar_cnt[t], 1u);
                if (tk == expected - 1u) {
                    atomicExch(&g_bar_rel[t], 1u);
                } else {
                    while (atomicAdd(&g_bar_rel[t], 0u) == 0u) __nanosleep(64);
                }
                __threadfence();
            }
            __syncthreads();
        }
    }
}

// ---------------------------------------------------------------------------
// Prep kernels
// ---------------------------------------------------------------------------
__global__ void sort_batches(const int* __restrict__ seq)
{
    __shared__ int hist[130];
    __shared__ int off[130];
    const int tid = threadIdx.x;
    if (tid < 130) hist[tid] = 0;
    if (tid < TT) { g_bar_cnt[tid] = 0; g_bar_rel[tid] = 0; }   // reset barriers each replay
    __syncthreads();
    for (int b = tid; b < BB; b += 256) atomicAdd(&hist[seq[b]], 1);
    __syncthreads();
    if (tid == 0) {
        int acc = 0;
        for (int v = 128; v >= 1; v--) { off[v] = acc; acc += hist[v]; }
    }
    __syncthreads();
    if (tid < TT) g_nact[tid] = (tid == 0) ? BB : off[tid];   // #seq > t
    __syncthreads();
    if (tid == 0) {
        for (int b = 0; b < BB; b++) {
            const int v = seq[b];
            const int p = off[v]++;
            g_perm[p] = b;
            g_seqp[p] = v;
        }
    }
}

__global__ void init_state(const float* __restrict__ c_in, const float* __restrict__ h_in)
{
    int i = blockIdx.x * blockDim.x + threadIdx.x;
    if (i < BB * HH) {
        const int bp = i / HH;
        const int hx = i - bp * HH;
        const size_t src = (size_t)g_perm[bp] * HH + hx;
        g_c[i] = c_in[src];
        float h = h_in[src];
        g_h[i] = h;
        g_h16[0][i] = __float2half(h);
    }
}

__global__ __launch_bounds__(256) void convert_x(const float* __restrict__ x)
{
    size_t i4 = (size_t)blockIdx.x * 256 + threadIdx.x;
    float4 v = *(const float4*)(x + i4 * 4);
    union { h16 h[4]; uint2 u; } H;
    H.h[0] = __float2half(v.x);
    H.h[1] = __float2half(v.y);
    H.h[2] = __float2half(v.z);
    H.h[3] = __float2half(v.w);
    *(uint2*)(g_x16 + i4 * 4) = H.u;
}

__global__ void transpose_split(const float* __restrict__ in, h16* __restrict__ oh,
                                h16* __restrict__ ol, int K, int N, int interleave)
{
    __shared__ float tile[32][33];
    const int kb = blockIdx.y * 32;
    const int nb = blockIdx.x * 32;
    const int tx = threadIdx.x;
    for (int r = threadIdx.y; r < 32; r += 8)
        tile[r][tx] = in[(size_t)(kb + r) * N + nb + tx];
    __syncthreads();
    for (int rr = threadIdx.y; rr < 32; rr += 8) {
        float v = tile[tx][rr];
        h16 hi, lo;
        splitw(v, hi, lo);
        int c = nb + rr;
        int n_new = interleave ? ((c & 1023) * 4 + (c >> 10)) : c;
        const size_t o = (size_t)n_new * K + kb + tx;
        oh[o] = hi;
        if (ol) ol[o] = lo;
    }
}

__global__ void permute_bias(const float* __restrict__ b)
{
    int c = blockIdx.x * 256 + threadIdx.x;
    if (c < FOURH) g_bias[(c & 1023) * 4 + (c >> 10)] = b[c];
}

// ---------------------------------------------------------------------------
// kernel_launch
// ---------------------------------------------------------------------------
extern "C" void kernel_launch(void* const* d_in, const int* in_sizes, int n_in,
                              void* d_out, int out_size)
{
    const float* X    = (const float*)d_in[0];
    const int*   seq  = (const int*)d_in[1];
    const float* c_in = (const float*)d_in[2];
    const float* h_in = (const float*)d_in[3];
    const float* W    = (const float*)d_in[4];
    const float* bias = (const float*)d_in[5];
    const float* Wout = (const float*)d_in[6];
    const float* bout = (const float*)d_in[7];
    float* out = (float*)d_out;

    h16 *p_wxh, *p_whh, *p_whl, *p_woh;
    cudaGetSymbolAddress((void**)&p_wxh, g_wx_hi);
    cudaGetSymbolAddress((void**)&p_whh, g_wh_hi);
    cudaGetSymbolAddress((void**)&p_whl, g_wh_lo);
    cudaGetSymbolAddress((void**)&p_woh, g_wo_hi);

    cudaFuncSetAttribute(gemm_xw, cudaFuncAttributeMaxDynamicSharedMemorySize, SMEM_X);
    cudaFuncSetAttribute(gemm_head, cudaFuncAttributeMaxDynamicSharedMemorySize, SMEM_X);
    cudaFuncSetAttribute(lstm_persistent, cudaFuncAttributeMaxDynamicSharedMemorySize, SMEM_REC);

    // prep
    sort_batches<<<1, 256>>>(seq);
    init_state<<<(BB * HH + 255) / 256, 256>>>(c_in, h_in);
    convert_x<<<(int)((size_t)BT * FF / 4 / 256), 256>>>(X);
    transpose_split<<<dim3(FOURH / 32, FF / 32), dim3(32, 8)>>>(W, p_wxh, nullptr, FF, FOURH, 1);
    transpose_split<<<dim3(FOURH / 32, HH / 32), dim3(32, 8)>>>(W + (size_t)FF * FOURH, p_whh, p_whl, HH, FOURH, 1);
    transpose_split<<<dim3(NOUT / 32, HH / 32), dim3(32, 8)>>>(Wout, p_woh, nullptr, HH, NOUT, 0);
    permute_bias<<<FOURH / 256, 256>>>(bias);

    // XW (skip tiles fully past seq end)
    gemm_xw<<<dim3(FOURH / 128, BT / 64), 256, SMEM_X>>>();

    // recurrence: single persistent launch, device-side per-step barriers
    lstm_persistent<<<dim3(NCTA_COL, NCTA_ROW), 256, SMEM_REC>>>();

    // head (skipped tiles write bias rows)
    gemm_head<<<dim3(NOUT / 128, BT / 64), 256, SMEM_X>>>(bout, out);
}

// round 11
// speedup vs baseline: 1.3303x; 1.3303x over previous
#include <cuda_runtime.h>
#include <cuda_fp16.h>
#include <math.h>
#include <stdint.h>

#define BB 512
#define TT 128
#define FF 1024
#define HH 1024
#define NOUT 256
#define FOURH 4096
#define BT 65536

typedef __half h16;

// ---------------------------------------------------------------------------
// Device-global scratch (sorted-batch order unless noted)
// ---------------------------------------------------------------------------
__device__ float g_xw[(size_t)BT * FOURH];     // X @ Wx + b, gate-interleaved cols
__device__ float g_c[BB * HH];
__device__ float g_h[BB * HH];
__device__ float g_bias[FOURH];                // permuted bias
__device__ h16   g_x16[(size_t)BT * FF];       // X as fp16 (ORIGINAL batch order)
__device__ h16   g_f16[(size_t)BT * HH];       // masked h outputs (zero-init; inactive rows never written)
__device__ h16   g_h16[2][BB * HH];            // double-buffered h state, fp16
__device__ h16   g_wx_hi[(size_t)FOURH * FF];  // Wx^T [4H,F] K-major, interleaved rows
__device__ h16   g_wh_hi[(size_t)FOURH * HH];
__device__ h16   g_wh_lo[(size_t)FOURH * HH];
__device__ h16   g_wo_hi[NOUT * HH];
__device__ int   g_perm[BB];                   // sorted idx -> original idx
__device__ int   g_seqp[BB];                   // seq_len in sorted order (descending)
__device__ int   g_nact[TT];                   // #batches with seq_len > t
__device__ int   g_rowoff[BB];                 // prefix sum of seqp
__device__ int   g_total[1];                   // total active rows
__device__ int   g_rows[BT + 64];              // packed i -> sorted flat row (bp*TT+t)
__device__ int   g_rowsrc[BT + 64];            // packed i -> original flat row (perm[bp]*TT+t)

// ---------------------------------------------------------------------------
// Baseline-PTX helpers (legal on plain sm_103 target)
// ---------------------------------------------------------------------------
__device__ __forceinline__ uint32_t smem_u32(const void* p) {
    uint32_t a;
    asm("{ .reg .u64 t; cvta.to.shared.u64 t, %1; cvt.u32.u64 %0, t; }"
        : "=r"(a) : "l"(p));
    return a;
}
__device__ __forceinline__ void cp16(uint32_t dst, const void* src) {
    asm volatile("cp.async.cg.shared.global [%0], [%1], 16;"
                 :: "r"(dst), "l"(src) : "memory");
}
__device__ __forceinline__ void ldsm4(uint32_t* r, uint32_t addr) {
    asm volatile("ldmatrix.sync.aligned.m8n8.x4.shared.b16 {%0,%1,%2,%3}, [%4];"
                 : "=r"(r[0]), "=r"(r[1]), "=r"(r[2]), "=r"(r[3]) : "r"(addr));
}
__device__ __forceinline__ void mma16816(float* d, const uint32_t* a, const uint32_t* b) {
    asm volatile(
        "mma.sync.aligned.m16n8k16.row.col.f32.f16.f16.f32 "
        "{%0,%1,%2,%3}, {%4,%5,%6,%7}, {%8,%9}, {%0,%1,%2,%3};"
        : "+f"(d[0]), "+f"(d[1]), "+f"(d[2]), "+f"(d[3])
        : "r"(a[0]), "r"(a[1]), "r"(a[2]), "r"(a[3]), "r"(b[0]), "r"(b[1]));
}

// ---------------------------------------------------------------------------
// GEMM tile machinery. BM=MT*32 rows, BN=NT*32 cols, BK=32, 256 threads
// (8 warps: 2 row-groups x 4 col-groups). NB = B terms. NST = stages.
// PACKED: A rows gathered through an index array.
// ---------------------------------------------------------------------------
#define ROWB 80

template <int MT, int NT, int NB, bool PACKED>
__device__ __forceinline__ void load_stage(
    uint32_t stg, const h16* __restrict__ A, const int* __restrict__ aidx,
    const h16* __restrict__ Bh, const h16* __restrict__ Bl,
    int n0, int k0, int K, int tid)
{
    constexpr int BM = MT * 32;
    constexpr int BN = NT * 32;
    constexpr uint32_t OFFB = (uint32_t)BM * ROWB;
    constexpr uint32_t BTERM = (uint32_t)BN * ROWB;
#pragma unroll
    for (int i = 0; i < BM * 4 / 256; i++) {
        const int c = tid + i * 256;
        const int row = c >> 2;
        const int seg = c & 3;
        const h16* src = PACKED ? A + (size_t)aidx[row] * K + k0 + seg * 8
                                : A + (size_t)row * K + k0 + seg * 8;
        cp16(stg + (uint32_t)(row * ROWB + seg * 16), src);
    }
#pragma unroll
    for (int i = 0; i < BN * 4 / 256; i++) {
        const int c = tid + i * 256;
        const int row = c >> 2;
        const int seg = c & 3;
        const uint32_t soff = (uint32_t)(row * ROWB + seg * 16);
        const size_t gb = (size_t)(n0 + row) * K + k0 + seg * 8;
        cp16(stg + OFFB + soff, Bh + gb);
        if (NB == 2) cp16(stg + OFFB + BTERM + soff, Bl + gb);
    }
}

template <int MT, int NT, int NB, int NST, bool PACKED>
__device__ __forceinline__ void gemm_mainloop(
    uint32_t SM, const h16* __restrict__ A, const int* __restrict__ aidx,
    const h16* __restrict__ Bh, const h16* __restrict__ Bl,
    int n0, int K, int tid, float acc[MT][NT][4])
{
    constexpr int BM = MT * 32;
    constexpr int BN = NT * 32;
    constexpr uint32_t OFFB = (uint32_t)BM * ROWB;
    constexpr uint32_t BTERM = (uint32_t)BN * ROWB;
    constexpr uint32_t STG_B = OFFB + NB * BTERM;
    const int lane = tid & 31;
    const int wid  = tid >> 5;
    const int wm   = wid & 1;
    const int wn   = wid >> 1;
    const int NC = K >> 5;

#pragma unroll
    for (int s = 0; s < NST - 1; s++) {
        load_stage<MT, NT, NB, PACKED>(SM + s * STG_B, A, aidx, Bh, Bl, n0, s * 32, K, tid);
        asm volatile("cp.async.commit_group;" ::: "memory");
    }

    const int arow = wm * (MT * 16) + (lane & 15);
    const uint32_t akoff = (uint32_t)((lane >> 4) * 16);
    const int bsel = lane >> 3;
    const int bn = wn * (NT * 8) + ((bsel >> 1) << 3) + (lane & 7);
    const uint32_t bkoff = (uint32_t)((bsel & 1) * 16);

    for (int it = 0; it < NC; it++) {
        asm volatile("cp.async.wait_group %0;" :: "n"(NST - 2) : "memory");
        __syncthreads();

        const int nx = it + NST - 1;
        if (nx < NC)
            load_stage<MT, NT, NB, PACKED>(SM + (uint32_t)(nx % NST) * STG_B,
                                           A, aidx, Bh, Bl, n0, nx * 32, K, tid);
        asm volatile("cp.async.commit_group;" ::: "memory");

        const uint32_t stg = SM + (uint32_t)(it % NST) * STG_B;
#pragma unroll
        for (int ks = 0; ks < 2; ks++) {
            uint32_t ah[MT][4], bh[NT][2], bl[NT][2];
            const uint32_t ak = (uint32_t)(ks * 32) + akoff;
#pragma unroll
            for (int mt = 0; mt < MT; mt++)
                ldsm4(ah[mt], stg + (uint32_t)((arow + mt * 16) * ROWB) + ak);
            const uint32_t bk = (uint32_t)(ks * 32) + bkoff;
#pragma unroll
            for (int np = 0; np < NT / 2; np++) {
                const uint32_t bd = stg + OFFB + (uint32_t)((bn + np * 16) * ROWB) + bk;
                uint32_t tr[4];
                ldsm4(tr, bd);
                bh[2 * np][0] = tr[0]; bh[2 * np][1] = tr[1];
                bh[2 * np + 1][0] = tr[2]; bh[2 * np + 1][1] = tr[3];
                if (NB == 2) {
                    ldsm4(tr, bd + BTERM);
                    bl[2 * np][0] = tr[0]; bl[2 * np][1] = tr[1];
                    bl[2 * np + 1][0] = tr[2]; bl[2 * np + 1][1] = tr[3];
                }
            }
#pragma unroll
            for (int mt = 0; mt < MT; mt++)
#pragma unroll
                for (int nt = 0; nt < NT; nt++) {
                    mma16816(acc[mt][nt], ah[mt], bh[nt]);
                    if (NB == 2) mma16816(acc[mt][nt], ah[mt], bl[nt]);
                }
        }
    }
}

// Scatter epilogue: per-row destination via rows[], valid rows only (+bias).
template <int MT, int NT>
__device__ __forceinline__ void store_scatter(
    float acc[MT][NT][4], float* __restrict__ Cbase, const int* __restrict__ rows,
    const float* __restrict__ bias, int N, int n0, int tid, int nvalid)
{
    const int lane = tid & 31;
    const int wid  = tid >> 5;
    const int wm   = wid & 1;
    const int wn   = wid >> 1;
    const int colq = (lane & 3) * 2;
    const int rowq = lane >> 2;
    float bx[NT], by[NT];
#pragma unroll
    for (int nt = 0; nt < NT; nt++) {
        const int col = wn * (NT * 8) + nt * 8 + colq;
        float2 bv = *(const float2*)(bias + n0 + col);
        bx[nt] = bv.x; by[nt] = bv.y;
    }
#pragma unroll
    for (int mt = 0; mt < MT; mt++) {
        const int r0 = wm * (MT * 16) + mt * 16 + rowq;
#pragma unroll
        for (int half = 0; half < 2; half++) {
            const int rloc = r0 + half * 8;
            if (rloc < nvalid) {
                float* C = Cbase + (size_t)rows[rloc] * N;
#pragma unroll
                for (int nt = 0; nt < NT; nt++) {
                    const int col = wn * (NT * 8) + nt * 8 + colq;
                    *(float2*)(C + n0 + col) =
                        make_float2(acc[mt][nt][2 * half] + bx[nt],
                                    acc[mt][nt][2 * half + 1] + by[nt]);
                }
            }
        }
    }
}

// ---------------------------------------------------------------------------
// Packed XW GEMM: active rows only. A gathered from g_x16 (original order),
// C scattered to g_xw (sorted order).
// ---------------------------------------------------------------------------
#define SMEM_X (4 * (64 * ROWB + 128 * ROWB))   // 61440
__global__ __launch_bounds__(256, 2)
void gemm_xw_packed()
{
    const int ts = blockIdx.y * 64;
    const int total = g_total[0];
    if (ts >= total) return;
    extern __shared__ char smem_raw[];
    const uint32_t SM = smem_u32(smem_raw);
    const int tid = threadIdx.x;
    const int n0 = blockIdx.x * 128;

    float acc[2][4][4];
#pragma unroll
    for (int a = 0; a < 2; a++)
#pragma unroll
        for (int b = 0; b < 4; b++)
#pragma unroll
            for (int cc = 0; cc < 4; cc++) acc[a][b][cc] = 0.0f;

    gemm_mainloop<2, 4, 1, 4, true>(SM, g_x16, g_rowsrc + ts, g_wx_hi, nullptr,
                                    n0, FF, tid, acc);
    store_scatter<2, 4>(acc, g_xw, g_rows + ts, g_bias, FOURH, n0, tid, total - ts);
}

// ---------------------------------------------------------------------------
// Packed head GEMM: A gathered from g_f16 (sorted), C scattered to out (original).
// ---------------------------------------------------------------------------
__global__ __launch_bounds__(256, 2)
void gemm_head_packed(const float* __restrict__ bout, float* __restrict__ out)
{
    const int ts = blockIdx.y * 64;
    const int total = g_total[0];
    if (ts >= total) return;
    extern __shared__ char smem_raw[];
    const uint32_t SM = smem_u32(smem_raw);
    const int tid = threadIdx.x;
    const int n0 = blockIdx.x * 128;

    float acc[2][4][4];
#pragma unroll
    for (int a = 0; a < 2; a++)
#pragma unroll
        for (int b = 0; b < 4; b++)
#pragma unroll
            for (int cc = 0; cc < 4; cc++) acc[a][b][cc] = 0.0f;

    gemm_mainloop<2, 4, 1, 4, true>(SM, g_f16, g_rows + ts, g_wo_hi, nullptr,
                                    n0, HH, tid, acc);
    store_scatter<2, 4>(acc, out, g_rowsrc + ts, bout, NOUT, n0, tid, total - ts);
}

// Bias fill for inactive head rows (logits = bias there).
__global__ void head_bias_fill(const float* __restrict__ bout, float* __restrict__ out)
{
    const int bp = blockIdx.x;
    const int s = g_seqp[bp];
    const int nrows = TT - s;
    if (nrows <= 0) return;
    const size_t base = ((size_t)g_perm[bp] * TT + s) * NOUT;
    for (int i = threadIdx.x; i < nrows * 64; i += 256) {
        const int r = i >> 6;
        const int c = (i & 63) * 4;
        *(float4*)(out + base + (size_t)r * NOUT + c) = *(const float4*)(bout + c);
    }
}

// ---------------------------------------------------------------------------
// Fused recurrent step: BM=64, BN=64 (NT=2), 2-term weights, 3 stages.
// Per-step launch; prefix-active skip; double-buffered h.
// ---------------------------------------------------------------------------
#define SMEM_REC (3 * (64 * ROWB + 2 * 64 * ROWB))   // 46080
__device__ __forceinline__ float sigf(float x) { return 1.0f / (1.0f + expf(-x)); }
__device__ __forceinline__ void splitw(float v, h16& hi, h16& lo) {
    hi = __float2half(v);
    lo = __float2half(v - __half2float(hi));
}

#define ZPITCH 68

__global__ __launch_bounds__(256, 2)
void lstm_step_fused(int t)
{
    const int m0 = blockIdx.y * 64;
    if (m0 >= g_nact[t]) return;

    extern __shared__ char smem_raw[];
    const uint32_t SM = smem_u32(smem_raw);
    float* zs = (float*)smem_raw;
    const int tid  = threadIdx.x;
    const int lane = tid & 31;
    const int wid  = tid >> 5;
    const int wm   = wid & 1;
    const int wn   = wid >> 1;
    const int n0 = blockIdx.x * 64;     // interleaved gate-col offset (BN=64)

    const h16* __restrict__ h_rd = g_h16[t & 1] + (size_t)m0 * HH;
    h16* __restrict__ h_wr = g_h16[(t + 1) & 1];

    float acc[2][2][4];
#pragma unroll
    for (int a = 0; a < 2; a++)
#pragma unroll
        for (int b = 0; b < 2; b++)
#pragma unroll
            for (int cc = 0; cc < 4; cc++) acc[a][b][cc] = 0.0f;

    gemm_mainloop<2, 2, 2, 3, false>(SM, h_rd, nullptr, g_wh_hi, g_wh_lo,
                                     n0, HH, tid, acc);

    __syncthreads();

    // acc -> smem z tile (64 x 64)
    const int colq = (lane & 3) * 2;
    const int rowq = lane >> 2;
#pragma unroll
    for (int nt = 0; nt < 2; nt++) {
        const int col = wn * 16 + nt * 8 + colq;
#pragma unroll
        for (int mt = 0; mt < 2; mt++) {
            const int r0 = wm * 32 + mt * 16 + rowq;
            *(float2*)&zs[r0 * ZPITCH + col] = make_float2(acc[mt][nt][0], acc[mt][nt][1]);
            *(float2*)&zs[(r0 + 8) * ZPITCH + col] = make_float2(acc[mt][nt][2], acc[mt][nt][3]);
        }
    }
    __syncthreads();

    // cell epilogue: 64 rows x 16 units
#pragma unroll
    for (int i = 0; i < 4; i++) {
        const int idx = i * 256 + tid;
        const int r = idx >> 4;
        const int u = idx & 15;
        const int b = m0 + r;
        const int hx = (n0 >> 2) + u;

        float4 z4 = *(float4*)&zs[r * ZPITCH + 4 * u];
        float4 x4 = *(const float4*)(g_xw + ((size_t)b * TT + t) * FOURH + n0 + 4 * u);

        const float zi = z4.x + x4.x;
        const float zj = z4.y + x4.y;
        const float zf = z4.z + x4.z;
        const float zo = z4.w + x4.w;

        const size_t si = (size_t)b * HH + hx;
        const float c = g_c[si];
        const float hprev = g_h[si];
        const bool m = t < g_seqp[b];

        const float nc = c * sigf(zf + 1.0f) + sigf(zi) * tanhf(zj);
        const float nh = tanhf(nc) * sigf(zo);

        const float co = m ? nc : c;
        const float ho = m ? nh : hprev;
        const float fe = m ? nh : 0.0f;

        g_c[si] = co;
        g_h[si] = ho;
        h_wr[si] = __float2half(ho);
        g_f16[((size_t)b * TT + t) * HH + hx] = __float2half(fe);
    }
}

// ---------------------------------------------------------------------------
// Prep kernels
// ---------------------------------------------------------------------------
__global__ void sort_batches(const int* __restrict__ seq)
{
    __shared__ int hist[130];
    __shared__ int off[130];
    const int tid = threadIdx.x;
    if (tid < 130) hist[tid] = 0;
    __syncthreads();
    for (int b = tid; b < BB; b += 256) atomicAdd(&hist[seq[b]], 1);
    __syncthreads();
    if (tid == 0) {
        int acc = 0;
        for (int v = 128; v >= 1; v--) { off[v] = acc; acc += hist[v]; }
    }
    __syncthreads();
    if (tid < TT) g_nact[tid] = (tid == 0) ? BB : off[tid];   // #seq > t
    __syncthreads();
    if (tid == 0) {
        for (int b = 0; b < BB; b++) {
            const int v = seq[b];
            const int p = off[v]++;
            g_perm[p] = b;
            g_seqp[p] = v;
        }
        int acc = 0;
        for (int b = 0; b < BB; b++) { g_rowoff[b] = acc; acc += g_seqp[b]; }
        g_total[0] = acc;
    }
}

__global__ void fill_rows()
{
    const int bp = blockIdx.x;
    const int s = g_seqp[bp];
    const int off = g_rowoff[bp];
    const int dst0 = bp * TT;
    const int src0 = g_perm[bp] * TT;
    for (int t = threadIdx.x; t < s; t += 128) {
        g_rows[off + t] = dst0 + t;
        g_rowsrc[off + t] = src0 + t;
    }
    if (bp == 0 && threadIdx.x < 64) {       // pad tail tile with safe row 0
        const int total = g_total[0];
        g_rows[total + threadIdx.x] = 0;
        g_rowsrc[total + threadIdx.x] = 0;
    }
}

__global__ void init_state(const float* __restrict__ c_in, const float* __restrict__ h_in)
{
    int i = blockIdx.x * blockDim.x + threadIdx.x;
    if (i < BB * HH) {
        const int bp = i / HH;
        const int hx = i - bp * HH;
        const size_t src = (size_t)g_perm[bp] * HH + hx;
        g_c[i] = c_in[src];
        float h = h_in[src];
        g_h[i] = h;
        g_h16[0][i] = __float2half(h);
    }
}

__global__ __launch_bounds__(256) void convert_x(const float* __restrict__ x)
{
    size_t i4 = (size_t)blockIdx.x * 256 + threadIdx.x;
    float4 v = *(const float4*)(x + i4 * 4);
    union { h16 h[4]; uint2 u; } H;
    H.h[0] = __float2half(v.x);
    H.h[1] = __float2half(v.y);
    H.h[2] = __float2half(v.z);
    H.h[3] = __float2half(v.w);
    *(uint2*)(g_x16 + i4 * 4) = H.u;
}

__global__ void transpose_split(const float* __restrict__ in, h16* __restrict__ oh,
                                h16* __restrict__ ol, int K, int N, int interleave)
{
    __shared__ float tile[32][33];
    const int kb = blockIdx.y * 32;
    const int nb = blockIdx.x * 32;
    const int tx = threadIdx.x;
    for (int r = threadIdx.y; r < 32; r += 8)
        tile[r][tx] = in[(size_t)(kb + r) * N + nb + tx];
    __syncthreads();
    for (int rr = threadIdx.y; rr < 32; rr += 8) {
        float v = tile[tx][rr];
        h16 hi, lo;
        splitw(v, hi, lo);
        int c = nb + rr;
        int n_new = interleave ? ((c & 1023) * 4 + (c >> 10)) : c;
        const size_t o = (size_t)n_new * K + kb + tx;
        oh[o] = hi;
        if (ol) ol[o] = lo;
    }
}

__global__ void permute_bias(const float* __restrict__ b)
{
    int c = blockIdx.x * 256 + threadIdx.x;
    if (c < FOURH) g_bias[(c & 1023) * 4 + (c >> 10)] = b[c];
}

// ---------------------------------------------------------------------------
// kernel_launch
// ---------------------------------------------------------------------------
extern "C" void kernel_launch(void* const* d_in, const int* in_sizes, int n_in,
                              void* d_out, int out_size)
{
    const float* X    = (const float*)d_in[0];
    const int*   seq  = (const int*)d_in[1];
    const float* c_in = (const float*)d_in[2];
    const float* h_in = (const float*)d_in[3];
    const float* W    = (const float*)d_in[4];
    const float* bias = (const float*)d_in[5];
    const float* Wout = (const float*)d_in[6];
    const float* bout = (const float*)d_in[7];
    float* out = (float*)d_out;

    h16 *p_wxh, *p_whh, *p_whl, *p_woh;
    cudaGetSymbolAddress((void**)&p_wxh, g_wx_hi);
    cudaGetSymbolAddress((void**)&p_whh, g_wh_hi);
    cudaGetSymbolAddress((void**)&p_whl, g_wh_lo);
    cudaGetSymbolAddress((void**)&p_woh, g_wo_hi);

    cudaFuncSetAttribute(gemm_xw_packed, cudaFuncAttributeMaxDynamicSharedMemorySize, SMEM_X);
    cudaFuncSetAttribute(gemm_head_packed, cudaFuncAttributeMaxDynamicSharedMemorySize, SMEM_X);
    cudaFuncSetAttribute(lstm_step_fused, cudaFuncAttributeMaxDynamicSharedMemorySize, SMEM_REC);

    // prep
    sort_batches<<<1, 256>>>(seq);
    fill_rows<<<BB, 128>>>();
    init_state<<<(BB * HH + 255) / 256, 256>>>(c_in, h_in);
    convert_x<<<(int)((size_t)BT * FF / 4 / 256), 256>>>(X);
    transpose_split<<<dim3(FOURH / 32, FF / 32), dim3(32, 8)>>>(W, p_wxh, nullptr, FF, FOURH, 1);
    transpose_split<<<dim3(FOURH / 32, HH / 32), dim3(32, 8)>>>(W + (size_t)FF * FOURH, p_whh, p_whl, HH, FOURH, 1);
    transpose_split<<<dim3(NOUT / 32, HH / 32), dim3(32, 8)>>>(Wout, p_woh, nullptr, HH, NOUT, 0);
    permute_bias<<<FOURH / 256, 256>>>(bias);

    // XW over packed active rows
    gemm_xw_packed<<<dim3(FOURH / 128, BT / 64), 256, SMEM_X>>>();

    // recurrence: per-step launches, BN=64 tiles, prefix-active skip
    for (int t = 0; t < TT; t++)
        lstm_step_fused<<<dim3(FOURH / 64, BB / 64), 256, SMEM_REC>>>(t);

    // head over packed active rows + bias fill for inactive rows
    head_bias_fill<<<BB, 256>>>(bout, out);
    gemm_head_packed<<<dim3(NOUT / 128, BT / 64), 256, SMEM_X>>>(bout, out);
}